// round 7
// baseline (speedup 1.0000x reference)
#include <cuda_runtime.h>
#include <cstdint>

#define M 8192
#define NWA 128         // 64-bit alive words (M/64)
#define NMS_T 0.3f

typedef unsigned long long u64;

// ---------------- device scratch (no runtime allocation allowed) ------------
__device__ float  g_d[M * 5];        // transformed detections (orig order)
__device__ u64    g_ckey[M];         // packed (key<<13 | idx) for valid entries
__device__ int    g_cnt;             // valid count (atomic; reset by nms)
__device__ int    g_V;               // valid count (published by sort)
__device__ float  g_ds[M * 5];       // sorted detections (first V rows)
__device__ float4 g_boxes[M];        // x1,y1,x2,y2 (sorted order, first V)

// ---------------- kernel 1: transform + score + compact valid ---------------
__global__ void prep_kernel(const float* __restrict__ det,
                            const float* __restrict__ off,
                            const float* __restrict__ scl,
                            const float* __restrict__ bnd) {
    int i = blockIdx.x * blockDim.x + threadIdx.x;
    if (i >= M) return;
    int w = i >> 10;
    const float* dp = det + i * 5;
    float d0 = off[w * 5 + 0] + dp[0] * scl[w * 5 + 0];
    float d1 = off[w * 5 + 1] + dp[1] * scl[w * 5 + 1];
    float d2 = off[w * 5 + 2] + dp[2] * scl[w * 5 + 2];
    float d3 = off[w * 5 + 3] + dp[3] * scl[w * 5 + 3];
    float d4 = off[w * 5 + 4] + dp[4] * scl[w * 5 + 4];
    float cx = dp[1], cy = dp[2];
    bool valid = (cx < bnd[w * 4 + 1]) && (cx > bnd[w * 4 + 0]) &&
                 (cy < bnd[w * 4 + 3]) && (cy > bnd[w * 4 + 2]);

    g_d[i * 5 + 0] = d0;
    g_d[i * 5 + 1] = d1;
    g_d[i * 5 + 2] = d2;
    g_d[i * 5 + 3] = d3;
    g_d[i * 5 + 4] = d4;

    // only entries with score>0 can be kept; others produce zero output rows
    if (valid && d0 > 0.0f) {
        unsigned key = ~(__float_as_uint(d0) | 0x80000000u);
        int pos = atomicAdd(&g_cnt, 1);
        g_ckey[pos] = ((u64)key << 13) | (u64)i;   // (score desc, idx asc)
    }
}

// ---------------- kernel 2: hybrid shuffle/smem bitonic sort + gather -------
extern "C" __global__ void __launch_bounds__(1024)
sort_kernel() {
    extern __shared__ u64 sv[];       // up to 8192 * 8B = 64KB dynamic
    int tid = threadIdx.x;
    int V = g_cnt;
    if (tid == 0) g_V = V;

    int P = 1024;
    while (P < V) P <<= 1;            // P in {1024..8192}
    int slots = P >> 10;

    for (int t = tid; t < P; t += 1024)
        sv[t] = (t < V) ? g_ckey[t] : ~0ull;
    __syncthreads();

    u64 r[8];

    // phase 1: k = 2..32 entirely in registers (all strides intra-warp)
#pragma unroll 4
    for (int i = 0; i < slots; i++) r[i] = sv[i * 1024 + tid];
    for (int k = 2; k <= 32; k <<= 1) {
        for (int s = k >> 1; s >= 1; s >>= 1) {
            for (int i = 0; i < slots; i++) {
                unsigned e = i * 1024 + tid;
                u64 o = __shfl_xor_sync(0xffffffffu, r[i], s);
                bool takeMin = (((e & s) == 0) == ((e & k) == 0));
                bool lt = r[i] < o;
                r[i] = (takeMin == lt) ? r[i] : o;
            }
        }
    }
#pragma unroll 4
    for (int i = 0; i < slots; i++) sv[i * 1024 + tid] = r[i];
    __syncthreads();

    // phase 2: k = 64..P, strides >=32 in smem, strides <=16 in registers
    for (int k = 64; k <= P; k <<= 1) {
        for (int s = k >> 1; s >= 32; s >>= 1) {
            for (int v = tid; v < (P >> 1); v += 1024) {
                int i = ((v & ~(s - 1)) << 1) | (v & (s - 1));
                int j = i + s;
                bool up = ((i & k) == 0);
                u64 a = sv[i], b = sv[j];
                if ((a > b) == up) { sv[i] = b; sv[j] = a; }
            }
            __syncthreads();
        }
#pragma unroll 4
        for (int i = 0; i < slots; i++) r[i] = sv[i * 1024 + tid];
        for (int s = 16; s >= 1; s >>= 1) {
            for (int i = 0; i < slots; i++) {
                unsigned e = i * 1024 + tid;
                u64 o = __shfl_xor_sync(0xffffffffu, r[i], s);
                bool takeMin = (((e & s) == 0) == ((e & k) == 0));
                bool lt = r[i] < o;
                r[i] = (takeMin == lt) ? r[i] : o;
            }
        }
#pragma unroll 4
        for (int i = 0; i < slots; i++) sv[i * 1024 + tid] = r[i];
        __syncthreads();
    }

    // gather sorted rows, build boxes
    for (int j = tid; j < V; j += 1024) {
        int idx = (int)(sv[j] & 0x1FFFu);
        float dd[5];
#pragma unroll
        for (int c = 0; c < 5; c++) {
            dd[c] = g_d[idx * 5 + c];
            g_ds[j * 5 + c] = dd[c];
        }
        g_boxes[j] = make_float4(dd[1] - 0.5f * dd[3], dd[2] - 0.5f * dd[4],
                                 dd[1] + 0.5f * dd[3], dd[2] + 0.5f * dd[4]);
    }
}

// ---------------- kernel 3: fused on-the-fly greedy NMS + output ------------
// one block, 1024 threads. boxes in smem; per round warp0 finds next 1-2 kept,
// everyone suppresses their own elements vs those kept boxes.
__global__ void __launch_bounds__(1024) nms_kernel(float* __restrict__ out) {
    extern __shared__ float4 sbox[];     // 8192 * 16B = 128KB dynamic
    __shared__ u64 aliveW[NWA];
    __shared__ u64 skeep[NWA];
    __shared__ int s_j1, s_j2;
    __shared__ float4 s_b1, s_b2;

    int t = threadIdx.x;
    int V = g_V;
    if (t == 0) {
        g_cnt = 0;                       // deterministic reset for next run
        s_j2 = -1;
        s_b2 = make_float4(0.f, 0.f, 0.f, 0.f);
    }
    int NWv = (V + 63) >> 6;
    if (t < NWA) {
        int rr = V - (t << 6);
        aliveW[t] = (rr >= 64) ? ~0ull : (rr <= 0 ? 0ull : ((1ull << rr) - 1ull));
        skeep[t] = 0ull;
    }
    for (int j = t; j < V; j += 1024) sbox[j] = g_boxes[j];

    // local alive bits for owned elements [8t, 8t+8)
    int base = t << 3;
    unsigned lA;
    {
        int rr = V - base;
        lA = (rr >= 8) ? 0xffu : (rr <= 0 ? 0u : ((1u << rr) - 1u));
    }
    __syncthreads();

    int cw = 0;   // cursor word (warp0 registers, uniform across lanes)
    while (true) {
        if (t < 32) {
            int j1 = -1;
            while (cw < NWv) {
                int w = cw + t;
                u64 word = (w < NWv) ? aliveW[w] : 0ull;
                unsigned ball = __ballot_sync(0xffffffffu, word != 0ull);
                if (ball) {
                    int lw = __ffs(ball) - 1;
                    u64 ww = __shfl_sync(0xffffffffu, word, lw);
                    cw += lw;
                    j1 = (cw << 6) + __ffsll((long long)ww) - 1;
                    break;
                }
                cw += 32;
            }
            if (j1 >= 0) {
                float4 b1 = sbox[j1];
                float a1 = fmaxf(b1.z - b1.x, 0.f) * fmaxf(b1.w - b1.y, 0.f);
                // lookahead: first alive j in (j1, j1+32] surviving j1 is the next kept
                int jc = j1 + 1 + t;
                bool cand = false;
                if (jc < V && ((aliveW[jc >> 6] >> (jc & 63)) & 1ull)) {
                    float4 bc = sbox[jc];
                    float ac = fmaxf(bc.z - bc.x, 0.f) * fmaxf(bc.w - bc.y, 0.f);
                    float iw = fmaxf(fminf(b1.z, bc.z) - fmaxf(b1.x, bc.x), 0.f);
                    float ih = fmaxf(fminf(b1.w, bc.w) - fmaxf(b1.y, bc.y), 0.f);
                    float inter = iw * ih;
                    cand = !(inter > NMS_T * fmaxf(a1 + ac - inter, 1e-9f));
                }
                unsigned ball = __ballot_sync(0xffffffffu, cand);
                int j2 = ball ? (j1 + 1 + __ffs(ball) - 1) : -1;
                if (t == 0) {
                    aliveW[j1 >> 6] &= ~(1ull << (j1 & 63));
                    skeep[j1 >> 6] |= 1ull << (j1 & 63);
                    if (j2 >= 0) {
                        aliveW[j2 >> 6] &= ~(1ull << (j2 & 63));
                        skeep[j2 >> 6] |= 1ull << (j2 & 63);
                        s_b2 = sbox[j2];
                    }
                    s_j1 = j1;
                    s_j2 = j2;
                    s_b1 = b1;
                }
                if (j2 >= 0) cw = j2 >> 6;
            } else if (t == 0) {
                s_j1 = -1;
            }
        }
        __syncthreads();

        int j1 = s_j1;
        if (j1 < 0) break;
        int j2 = s_j2;
        float4 b1 = s_b1, b2 = s_b2;

        if (lA) {
            float a1 = fmaxf(b1.z - b1.x, 0.f) * fmaxf(b1.w - b1.y, 0.f);
            float a2 = (j2 >= 0) ? fmaxf(b2.z - b2.x, 0.f) * fmaxf(b2.w - b2.y, 0.f) : 0.f;
            unsigned clr = 0;
#pragma unroll
            for (int s = 0; s < 8; s++) {
                if ((lA >> s) & 1u) {
                    int j = base + s;
                    if (j == j1 || j == j2) { clr |= 1u << s; continue; }
                    if (j < j1) continue;         // already-dead region (unreachable)
                    float4 b = sbox[j];
                    float ab = fmaxf(b.z - b.x, 0.f) * fmaxf(b.w - b.y, 0.f);
                    float iw = fmaxf(fminf(b1.z, b.z) - fmaxf(b1.x, b.x), 0.f);
                    float ih = fmaxf(fminf(b1.w, b.w) - fmaxf(b1.y, b.y), 0.f);
                    float inter = iw * ih;
                    bool sup = inter > NMS_T * fmaxf(a1 + ab - inter, 1e-9f);
                    if (!sup && j2 >= 0 && j > j2) {
                        iw = fmaxf(fminf(b2.z, b.z) - fmaxf(b2.x, b.x), 0.f);
                        ih = fmaxf(fminf(b2.w, b.w) - fmaxf(b2.y, b.y), 0.f);
                        inter = iw * ih;
                        sup = inter > NMS_T * fmaxf(a2 + ab - inter, 1e-9f);
                    }
                    if (sup) clr |= 1u << s;
                }
            }
            if (clr) {
                lA &= ~clr;
                atomicAnd(&aliveW[t >> 3], ~((u64)clr << ((t & 7) << 3)));
            }
        }
        __syncthreads();
    }

    // fused masked output
    for (int j = t; j < M; j += 1024) {
        if (j < V) {
            float f = ((skeep[j >> 6] >> (j & 63)) & 1ull) ? 1.0f : 0.0f;
#pragma unroll
            for (int c = 0; c < 5; c++)
                out[j * 5 + c] = g_ds[j * 5 + c] * f;
        } else {
#pragma unroll
            for (int c = 0; c < 5; c++)
                out[j * 5 + c] = 0.0f;
        }
    }
}

// ---------------- launcher ---------------------------------------------------
extern "C" void kernel_launch(void* const* d_in, const int* in_sizes, int n_in,
                              void* d_out, int out_size) {
    const float* det = (const float*)d_in[0];
    const float* off = (const float*)d_in[1];
    const float* scl = (const float*)d_in[2];
    const float* bnd = (const float*)d_in[3];
    float* out = (float*)d_out;

    cudaFuncSetAttribute((const void*)sort_kernel,
                         cudaFuncAttributeMaxDynamicSharedMemorySize, 65536);
    cudaFuncSetAttribute((const void*)nms_kernel,
                         cudaFuncAttributeMaxDynamicSharedMemorySize, M * sizeof(float4));

    prep_kernel<<<M / 256, 256>>>(det, off, scl, bnd);
    sort_kernel<<<1, 1024, 65536>>>();
    nms_kernel<<<1, 1024, M * sizeof(float4)>>>(out);
}

// round 8
// speedup vs baseline: 1.7233x; 1.7233x over previous
#include <cuda_runtime.h>
#include <cstdint>

#define M 8192
#define NW 128          // 64-bit words per row (M/64)
#define NMS_T 0.3f
#define CH 256          // scan chunk size (elements)
#define WPC 4           // words per chunk (CH/64)

typedef unsigned long long u64;

// ---------------- device scratch (no runtime allocation allowed) ------------
__device__ float  g_d[M * 5];        // transformed detections (orig order)
__device__ int    g_V;               // valid count
__device__ float  g_ds[M * 5];       // sorted detections (first V rows)
__device__ float4 g_boxes[M];        // x1,y1,x2,y2 (sorted order, first V)
__device__ __align__(16) u64 g_mask[M * NW];   // suppression bitmask (i>j bits)

// ---------------- hybrid bitonic sort (compile-time size) -------------------
template <int SLOTS>
__device__ __forceinline__ void bitonic_sort(u64* sv, int tid) {
    const int P = SLOTS * 1024;
    u64 r[SLOTS];

    // phase 1: k = 2..32 entirely in registers (all strides intra-warp)
#pragma unroll
    for (int i = 0; i < SLOTS; i++) r[i] = sv[i * 1024 + tid];
#pragma unroll
    for (int k = 2; k <= 32; k <<= 1) {
#pragma unroll
        for (int s = k >> 1; s >= 1; s >>= 1) {
#pragma unroll
            for (int i = 0; i < SLOTS; i++) {
                unsigned e = i * 1024 + tid;
                u64 o = __shfl_xor_sync(0xffffffffu, r[i], s);
                bool takeMin = (((e & s) == 0) == ((e & k) == 0));
                r[i] = ((r[i] < o) == takeMin) ? r[i] : o;
            }
        }
    }
#pragma unroll
    for (int i = 0; i < SLOTS; i++) sv[i * 1024 + tid] = r[i];
    __syncthreads();

    // phase 2: k = 64..P; strides >=32 in smem, <=16 in registers
#pragma unroll
    for (int k = 64; k <= P; k <<= 1) {
        for (int s = k >> 1; s >= 32; s >>= 1) {
#pragma unroll
            for (int i = 0; i < SLOTS / 2; i++) {
                int v = i * 1024 + tid;
                int a = ((v & ~(s - 1)) << 1) | (v & (s - 1));
                int b = a + s;
                bool up = ((a & k) == 0);
                u64 x = sv[a], y = sv[b];
                if ((x > y) == up) { sv[a] = y; sv[b] = x; }
            }
            __syncthreads();
        }
#pragma unroll
        for (int i = 0; i < SLOTS; i++) r[i] = sv[i * 1024 + tid];
#pragma unroll
        for (int s = 16; s >= 1; s >>= 1) {
#pragma unroll
            for (int i = 0; i < SLOTS; i++) {
                unsigned e = i * 1024 + tid;
                u64 o = __shfl_xor_sync(0xffffffffu, r[i], s);
                bool takeMin = (((e & s) == 0) == ((e & k) == 0));
                r[i] = ((r[i] < o) == takeMin) ? r[i] : o;
            }
        }
#pragma unroll
        for (int i = 0; i < SLOTS; i++) sv[i * 1024 + tid] = r[i];
        __syncthreads();
    }
}

// ---------------- kernel 1: fused prep + compact + sort + gather ------------
extern "C" __global__ void __launch_bounds__(1024)
sortprep_kernel(const float* __restrict__ det, const float* __restrict__ off,
                const float* __restrict__ scl, const float* __restrict__ bnd) {
    extern __shared__ u64 sv[];       // 8192 * 8B = 64KB dynamic
    __shared__ int scnt;
    int tid = threadIdx.x;
    int lane = tid & 31;
    if (tid == 0) scnt = 0;
    __syncthreads();

    // prep: 8 rows per thread, warp-aggregated compaction into smem
#pragma unroll
    for (int rr = 0; rr < 8; rr++) {
        int i = tid + rr * 1024;
        int w = i >> 10;
        float a0 = det[i * 5 + 0], a1 = det[i * 5 + 1], a2 = det[i * 5 + 2];
        float a3 = det[i * 5 + 3], a4 = det[i * 5 + 4];
        float d0 = off[w * 5 + 0] + a0 * scl[w * 5 + 0];
        float d1 = off[w * 5 + 1] + a1 * scl[w * 5 + 1];
        float d2 = off[w * 5 + 2] + a2 * scl[w * 5 + 2];
        float d3 = off[w * 5 + 3] + a3 * scl[w * 5 + 3];
        float d4 = off[w * 5 + 4] + a4 * scl[w * 5 + 4];
        bool valid = (a1 < bnd[w * 4 + 1]) && (a1 > bnd[w * 4 + 0]) &&
                     (a2 < bnd[w * 4 + 3]) && (a2 > bnd[w * 4 + 2]);
        g_d[i * 5 + 0] = d0;
        g_d[i * 5 + 1] = d1;
        g_d[i * 5 + 2] = d2;
        g_d[i * 5 + 3] = d3;
        g_d[i * 5 + 4] = d4;

        bool take = valid && d0 > 0.0f;    // non-positive scores yield zero rows
        unsigned ball = __ballot_sync(0xffffffffu, take);
        if (ball) {
            int nb = __popc(ball);
            int leader = __ffs(ball) - 1;
            int base = 0;
            if (lane == leader) base = atomicAdd(&scnt, nb);
            base = __shfl_sync(0xffffffffu, base, leader);
            if (take) {
                int o = __popc(ball & ((1u << lane) - 1));
                unsigned key = ~(__float_as_uint(d0) | 0x80000000u);
                sv[base + o] = ((u64)key << 13) | (u64)i;   // (score desc, idx asc)
            }
        }
    }
    __syncthreads();
    int V = scnt;
    if (tid == 0) g_V = V;

    if (V <= 4096) {
        for (int t = tid; t < 4096; t += 1024) if (t >= V) sv[t] = ~0ull;
        __syncthreads();
        bitonic_sort<4>(sv, tid);
    } else {
        for (int t = tid; t < 8192; t += 1024) if (t >= V) sv[t] = ~0ull;
        __syncthreads();
        bitonic_sort<8>(sv, tid);
    }

    // gather sorted rows, build boxes
    for (int j = tid; j < V; j += 1024) {
        int idx = (int)(sv[j] & 0x1FFFu);
        float dd[5];
#pragma unroll
        for (int c = 0; c < 5; c++) {
            dd[c] = g_d[idx * 5 + c];
            g_ds[j * 5 + c] = dd[c];
        }
        g_boxes[j] = make_float4(dd[1] - 0.5f * dd[3], dd[2] - 0.5f * dd[4],
                                 dd[1] + 0.5f * dd[3], dd[2] + 0.5f * dd[4]);
    }
}

// ---------------- kernel 2: IoU suppression bitmask (128x128 tiles) ---------
__global__ void __launch_bounds__(128) mask_kernel() {
    int bx = blockIdx.x, by = blockIdx.y;
    if (bx < by) return;                       // only i > j bits needed
    int V = g_V;
    if ((by << 7) >= V || (bx << 7) >= V) return;

    __shared__ float4 cbox[128];
    __shared__ float  carea[128];
    int t = threadIdx.x;
    int ci = (bx << 7) + t;
    float4 cb = (ci < V) ? g_boxes[ci] : make_float4(-4.f, -4.f, -4.f, -4.f);
    cbox[t] = cb;
    carea[t] = fmaxf(cb.z - cb.x, 0.f) * fmaxf(cb.w - cb.y, 0.f);
    __syncthreads();

    int j = (by << 7) + t;
    if (j >= V) return;
    float4 rb = g_boxes[j];
    float  ra = fmaxf(rb.z - rb.x, 0.f) * fmaxf(rb.w - rb.y, 0.f);

    u64 w0 = 0ull, w1 = 0ull;
#pragma unroll
    for (int b = 0; b < 64; b++) {
        int i = (bx << 7) + b;
        if (i > j) {
            float iw = fmaxf(fminf(rb.z, cbox[b].z) - fmaxf(rb.x, cbox[b].x), 0.f);
            float ih = fmaxf(fminf(rb.w, cbox[b].w) - fmaxf(rb.y, cbox[b].y), 0.f);
            float inter = iw * ih;
            if (inter > NMS_T * fmaxf(ra + carea[b] - inter, 1e-9f)) w0 |= 1ull << b;
        }
    }
#pragma unroll
    for (int b = 0; b < 64; b++) {
        int i = (bx << 7) + 64 + b;
        if (i > j) {
            float iw = fmaxf(fminf(rb.z, cbox[64 + b].z) - fmaxf(rb.x, cbox[64 + b].x), 0.f);
            float ih = fmaxf(fminf(rb.w, cbox[64 + b].w) - fmaxf(rb.y, cbox[64 + b].y), 0.f);
            float inter = iw * ih;
            if (inter > NMS_T * fmaxf(ra + carea[64 + b] - inter, 1e-9f)) w1 |= 1ull << b;
        }
    }
    *(ulonglong2*)&g_mask[(size_t)j * NW + (bx << 1)] = make_ulonglong2(w0, w1);
}

// ---------------- kernel 3: greedy NMS scan (speculative) + fused output ----
__global__ void __launch_bounds__(512) scan_kernel(float* __restrict__ out) {
    __shared__ u64 remv[NW];
    __shared__ u64 skeep[NW];
    __shared__ u64 sdiag[CH][WPC];        // 8KB diagonal block
    __shared__ u64 part[512];
    __shared__ unsigned short klist[CH];
    __shared__ int knum;
    int t = threadIdx.x;
    int V = g_V;
    int NC = (V + CH - 1) / CH;
    int NWv = (V + 63) >> 6;

    if (t < NW) { remv[t] = 0ull; skeep[t] = 0ull; }
    part[t] = 0ull;

    // prefetch diag block of chunk 0 (row = i>>2, word = i&3)
    u64 dp0 = 0ull, dp1 = 0ull;
    if (NC > 0) {
        dp0 = g_mask[(size_t)(t >> 2) * NW + (t & 3)];
        dp1 = g_mask[(size_t)((t + 512) >> 2) * NW + ((t + 512) & 3)];
    }
    __syncthreads();

    for (int c = 0; c < NC; c++) {
        sdiag[t >> 2][t & 3] = dp0;
        sdiag[(t + 512) >> 2][(t + 512) & 3] = dp1;
        // fold prev chunk's propagation partials: word c*WPC + f
        if (t < NW) {
            int w = c * WPC + t;
            if (w < NW)
                remv[w] |= (part[t * 4] | part[t * 4 + 1]) |
                           (part[t * 4 + 2] | part[t * 4 + 3]);
        }
        __syncthreads();

        // prefetch next chunk's diag block
        if (c + 1 < NC) {
            int base = (c + 1) * CH;
            dp0 = g_mask[(size_t)(base + (t >> 2)) * NW + ((c + 1) * WPC + (t & 3))];
            dp1 = g_mask[(size_t)(base + ((t + 512) >> 2)) * NW + ((c + 1) * WPC + ((t + 512) & 3))];
        }

        if (t == 0) {
            u64 alive[WPC], kept[WPC];
#pragma unroll
            for (int u = 0; u < WPC; u++) {
                int rb = V - ((c * WPC + u) << 6);
                u64 vm = (rb >= 64) ? ~0ull : (rb <= 0 ? 0ull : ((1ull << rb) - 1ull));
                alive[u] = ~remv[c * WPC + u] & vm;
                kept[u] = 0ull;
            }
            int n = 0;
            int rr = -1;
#pragma unroll
            for (int u = WPC - 1; u >= 0; u--)
                if (alive[u]) rr = (u << 6) + __ffsll((long long)alive[u]) - 1;

            bool have = false;
            u64 p0 = 0, p1 = 0, p2 = 0, p3 = 0;
            while (rr >= 0) {
                u64 r0, r1, r2, r3;
                if (have) { r0 = p0; r1 = p1; r2 = p2; r3 = p3; }
                else { r0 = sdiag[rr][0]; r1 = sdiag[rr][1];
                       r2 = sdiag[rr][2]; r3 = sdiag[rr][3]; }
                int wrr = rr >> 6;
                u64 brr = 1ull << (rr & 63);
                // clear rr from alive (pre-row state)
#pragma unroll
                for (int u = 0; u < WPC; u++) if (u == wrr) alive[u] &= ~brr;
                // speculative next (independent of row(rr) contents)
                int rs = -1;
#pragma unroll
                for (int u = WPC - 1; u >= 0; u--)
                    if (alive[u]) rs = (u << 6) + __ffsll((long long)alive[u]) - 1;
                if (rs >= 0) { p0 = sdiag[rs][0]; p1 = sdiag[rs][1];
                               p2 = sdiag[rs][2]; p3 = sdiag[rs][3]; }
                // commit rr
#pragma unroll
                for (int u = 0; u < WPC; u++) if (u == wrr) kept[u] |= brr;
                klist[n++] = (unsigned short)rr;
                // apply suppression row
                alive[0] &= ~r0; alive[1] &= ~r1; alive[2] &= ~r2; alive[3] &= ~r3;
                // speculation check
                if (rs >= 0) {
                    u64 x = 0;
                    int ws = rs >> 6;
#pragma unroll
                    for (int u = 0; u < WPC; u++) if (u == ws) x = alive[u];
                    if ((x >> (rs & 63)) & 1ull) { rr = rs; have = true; continue; }
                }
                rr = -1;
#pragma unroll
                for (int u = WPC - 1; u >= 0; u--)
                    if (alive[u]) rr = (u << 6) + __ffsll((long long)alive[u]) - 1;
                have = false;
            }
#pragma unroll
            for (int u = 0; u < WPC; u++) skeep[c * WPC + u] = kept[u];
            knum = n;
        }
        __syncthreads();

        // propagation to all later words: 4 threads/word, 4 accumulators
        {
            int w = (c + 1) * WPC + (t >> 2);
            int sub = t & 3;
            u64 a0 = 0ull, a1 = 0ull, a2 = 0ull, a3 = 0ull;
            if (w < NWv) {
                const u64* bp = g_mask + (size_t)(c * CH) * NW + w;
                int n = knum;
                int i = sub;
                for (; i + 12 < n; i += 16) {
                    a0 |= bp[(size_t)klist[i] * NW];
                    a1 |= bp[(size_t)klist[i + 4] * NW];
                    a2 |= bp[(size_t)klist[i + 8] * NW];
                    a3 |= bp[(size_t)klist[i + 12] * NW];
                }
                for (; i < n; i += 4) a0 |= bp[(size_t)klist[i] * NW];
            }
            part[t] = (a0 | a1) | (a2 | a3);
        }
        __syncthreads();
    }

    // fused masked output
    for (int j = t; j < M; j += 512) {
        if (j < V) {
            float f = ((skeep[j >> 6] >> (j & 63)) & 1ull) ? 1.0f : 0.0f;
#pragma unroll
            for (int c5 = 0; c5 < 5; c5++)
                out[j * 5 + c5] = g_ds[j * 5 + c5] * f;
        } else {
#pragma unroll
            for (int c5 = 0; c5 < 5; c5++)
                out[j * 5 + c5] = 0.0f;
        }
    }
}

// ---------------- launcher ---------------------------------------------------
extern "C" void kernel_launch(void* const* d_in, const int* in_sizes, int n_in,
                              void* d_out, int out_size) {
    const float* det = (const float*)d_in[0];
    const float* off = (const float*)d_in[1];
    const float* scl = (const float*)d_in[2];
    const float* bnd = (const float*)d_in[3];
    float* out = (float*)d_out;

    cudaFuncSetAttribute((const void*)sortprep_kernel,
                         cudaFuncAttributeMaxDynamicSharedMemorySize, 65536);

    sortprep_kernel<<<1, 1024, 65536>>>(det, off, scl, bnd);
    mask_kernel<<<dim3(64, 64), 128>>>();
    scan_kernel<<<1, 512>>>(out);
}

// round 9
// speedup vs baseline: 2.5743x; 1.4939x over previous
#include <cuda_runtime.h>
#include <cstdint>

#define M 8192
#define NW 128          // 64-bit words per row (M/64)
#define NMS_T 0.3f
#define CH 256          // scan chunk size (elements)
#define WPC 4           // words per chunk (CH/64)
#define TILE 2048       // sort tile size
#define NTILE 4         // number of sort tiles (M/TILE)

typedef unsigned long long u64;

// ---------------- device scratch (no runtime allocation allowed) ------------
__device__ float  g_d[M * 5];        // transformed detections (orig order)
__device__ u64    g_ckey[M];         // packed (key<<13 | idx), padded to 8192
__device__ int    g_cnt;             // valid count (atomic; reset by scan)
__device__ int    g_V;               // valid count (published by lsort)
__device__ float  g_ds[M * 5];       // sorted detections (first V rows)
__device__ float4 g_boxes[M];        // x1,y1,x2,y2 (sorted order, first V)
__device__ u64    g_mask[M * NW];    // suppression bitmask (i>j bits only)

// ---------------- kernel 1: transform + score + compact (coalesced) ---------
__global__ void __launch_bounds__(256)
prep_kernel(const float* __restrict__ det, const float* __restrict__ off,
            const float* __restrict__ scl, const float* __restrict__ bnd) {
    __shared__ float srow[256 * 5];
    int b = blockIdx.x;                    // 32 blocks x 256 rows
    int tid = threadIdx.x;
    int lane = tid & 31;
    const float* src = det + b * 256 * 5;
    for (int i = tid; i < 256 * 5; i += 256) srow[i] = src[i];
    __syncthreads();

    int i = b * 256 + tid;                 // global row
    int w = i >> 10;
    float a0 = srow[tid * 5 + 0], a1 = srow[tid * 5 + 1], a2 = srow[tid * 5 + 2];
    float a3 = srow[tid * 5 + 3], a4 = srow[tid * 5 + 4];
    float d0 = off[w * 5 + 0] + a0 * scl[w * 5 + 0];
    float d1 = off[w * 5 + 1] + a1 * scl[w * 5 + 1];
    float d2 = off[w * 5 + 2] + a2 * scl[w * 5 + 2];
    float d3 = off[w * 5 + 3] + a3 * scl[w * 5 + 3];
    float d4 = off[w * 5 + 4] + a4 * scl[w * 5 + 4];
    bool valid = (a1 < bnd[w * 4 + 1]) && (a1 > bnd[w * 4 + 0]) &&
                 (a2 < bnd[w * 4 + 3]) && (a2 > bnd[w * 4 + 2]);

    g_d[i * 5 + 0] = d0;
    g_d[i * 5 + 1] = d1;
    g_d[i * 5 + 2] = d2;
    g_d[i * 5 + 3] = d3;
    g_d[i * 5 + 4] = d4;

    bool take = valid && d0 > 0.0f;        // non-positive scores -> zero rows
    unsigned ball = __ballot_sync(0xffffffffu, take);
    if (ball) {
        int nb = __popc(ball);
        int leader = __ffs(ball) - 1;
        int base = 0;
        if (lane == leader) base = atomicAdd(&g_cnt, nb);
        base = __shfl_sync(0xffffffffu, base, leader);
        if (take) {
            int o = __popc(ball & ((1u << lane) - 1));
            unsigned key = ~(__float_as_uint(d0) | 0x80000000u);
            g_ckey[base + o] = ((u64)key << 13) | (u64)i;  // (score desc, idx asc)
        }
    }
}

// ---------------- kernel 2a: local bitonic sort of 2048-tiles ---------------
__global__ void __launch_bounds__(1024) lsort_kernel() {
    __shared__ u64 sv[TILE];
    int tb = blockIdx.x << 11;
    int tid = threadIdx.x;
    int V = g_cnt;
    if (tb == 0 && tid == 0) g_V = V;

    if (tb >= V) {                         // pure padding tile: just materialize
        g_ckey[tb + tid] = ~0ull;
        g_ckey[tb + tid + 1024] = ~0ull;
        return;
    }

    u64 r0 = (tb + tid < V) ? g_ckey[tb + tid] : ~0ull;
    u64 r1 = (tb + tid + 1024 < V) ? g_ckey[tb + tid + 1024] : ~0ull;

    // phase A: k = 2..32 entirely in registers (intra-warp shuffles)
    int e0 = tb + tid, e1 = tb + 1024 + tid;
#pragma unroll
    for (int k = 2; k <= 32; k <<= 1) {
#pragma unroll
        for (int s = k >> 1; s >= 1; s >>= 1) {
            u64 o0 = __shfl_xor_sync(0xffffffffu, r0, s);
            u64 o1 = __shfl_xor_sync(0xffffffffu, r1, s);
            bool m0 = (((e0 & s) == 0) == ((e0 & k) == 0));
            bool m1 = (((e1 & s) == 0) == ((e1 & k) == 0));
            r0 = ((r0 < o0) == m0) ? r0 : o0;
            r1 = ((r1 < o1) == m1) ? r1 : o1;
        }
    }
    sv[tid] = r0;
    sv[tid + 1024] = r1;
    __syncthreads();

    // phase B: k = 64..2048 (strides >=32 in smem, <=16 via shuffles)
#pragma unroll
    for (int k = 64; k <= TILE; k <<= 1) {
        for (int s = k >> 1; s >= 32; s >>= 1) {
            int a = ((tid & ~(s - 1)) << 1) | (tid & (s - 1));
            bool up = (((tb + a) & k) == 0);
            u64 x = sv[a], y = sv[a + s];
            if ((x > y) == up) { sv[a] = y; sv[a + s] = x; }
            __syncthreads();
        }
        r0 = sv[tid];
        r1 = sv[tid + 1024];
#pragma unroll
        for (int s = 16; s >= 1; s >>= 1) {
            u64 o0 = __shfl_xor_sync(0xffffffffu, r0, s);
            u64 o1 = __shfl_xor_sync(0xffffffffu, r1, s);
            bool m0 = (((e0 & s) == 0) == ((e0 & k) == 0));
            bool m1 = (((e1 & s) == 0) == ((e1 & k) == 0));
            r0 = ((r0 < o0) == m0) ? r0 : o0;
            r1 = ((r1 < o1) == m1) ? r1 : o1;
        }
        if (k < TILE) {
            sv[tid] = r0;
            sv[tid + 1024] = r1;
            __syncthreads();
        }
    }
    g_ckey[tb + tid] = r0;
    g_ckey[tb + 1024 + tid] = r1;
}

// ---------------- kernel 2b: global compare-exchange stage ------------------
__global__ void __launch_bounds__(512) gmerge_kernel(int k, int s) {
    int v = blockIdx.x * 512 + threadIdx.x;       // 4096 pairs
    int a = ((v & ~(s - 1)) << 1) | (v & (s - 1));
    int b = a + s;
    bool up = ((a & k) == 0);
    u64 x = g_ckey[a], y = g_ckey[b];
    if ((x > y) == up) { g_ckey[a] = y; g_ckey[b] = x; }
}

// ---------------- kernel 2c: intra-tile merge (strides <=1024) --------------
template <int K, bool FINAL>
__global__ void __launch_bounds__(1024) lmerge_kernel() {
    __shared__ u64 sv[TILE];
    int tb = blockIdx.x << 11;
    int tid = threadIdx.x;
    sv[tid] = g_ckey[tb + tid];
    sv[tid + 1024] = g_ckey[tb + tid + 1024];
    __syncthreads();

    for (int s = 1024; s >= 32; s >>= 1) {
        int a = ((tid & ~(s - 1)) << 1) | (tid & (s - 1));
        bool up = (((tb + a) & K) == 0);
        u64 x = sv[a], y = sv[a + s];
        if ((x > y) == up) { sv[a] = y; sv[a + s] = x; }
        __syncthreads();
    }
    u64 r0 = sv[tid], r1 = sv[tid + 1024];
    int e0 = tb + tid, e1 = tb + 1024 + tid;
#pragma unroll
    for (int s = 16; s >= 1; s >>= 1) {
        u64 o0 = __shfl_xor_sync(0xffffffffu, r0, s);
        u64 o1 = __shfl_xor_sync(0xffffffffu, r1, s);
        bool m0 = (((e0 & s) == 0) == ((e0 & K) == 0));
        bool m1 = (((e1 & s) == 0) == ((e1 & K) == 0));
        r0 = ((r0 < o0) == m0) ? r0 : o0;
        r1 = ((r1 < o1) == m1) ? r1 : o1;
    }

    if (FINAL) {
        sv[tid] = r0;
        sv[tid + 1024] = r1;
        __syncthreads();
        // fused gather: build sorted rows + boxes for this tile
        int V = g_V;
        for (int l = tid; l < TILE; l += 1024) {
            int j = tb + l;
            if (j < V) {
                int idx = (int)(sv[l] & 0x1FFFu);
                float dd[5];
#pragma unroll
                for (int c = 0; c < 5; c++) {
                    dd[c] = g_d[idx * 5 + c];
                    g_ds[j * 5 + c] = dd[c];
                }
                g_boxes[j] = make_float4(dd[1] - 0.5f * dd[3], dd[2] - 0.5f * dd[4],
                                         dd[1] + 0.5f * dd[3], dd[2] + 0.5f * dd[4]);
            }
        }
    } else {
        g_ckey[tb + tid] = r0;
        g_ckey[tb + 1024 + tid] = r1;
    }
}

// ---------------- kernel 3: IoU suppression bitmask (64x64 tiles) -----------
__global__ void mask_kernel() {
    int bx = blockIdx.x, by = blockIdx.y;
    if (bx < by) return;                       // only i > j bits needed
    int V = g_V;
    if ((by << 6) >= V || (bx << 6) >= V) return;

    __shared__ float4 cbox[64];
    __shared__ float  carea[64];
    int t = threadIdx.x;
    int ci = (bx << 6) + t;
    if (ci < V) {
        cbox[t] = g_boxes[ci];
        float4 cb = cbox[t];
        carea[t] = fmaxf(cb.z - cb.x, 0.f) * fmaxf(cb.w - cb.y, 0.f);
    } else {
        cbox[t] = make_float4(0.f, 0.f, 0.f, 0.f);
        carea[t] = 0.f;
    }
    __syncthreads();

    int j = (by << 6) + t;
    if (j >= V) return;
    float4 rb = g_boxes[j];
    float  ra = fmaxf(rb.z - rb.x, 0.f) * fmaxf(rb.w - rb.y, 0.f);

    u64 bits = 0ull;
#pragma unroll
    for (int b = 0; b < 64; b++) {
        int i = (bx << 6) + b;
        if (i > j) {
            float iw = fmaxf(fminf(rb.z, cbox[b].z) - fmaxf(rb.x, cbox[b].x), 0.f);
            float ih = fmaxf(fminf(rb.w, cbox[b].w) - fmaxf(rb.y, cbox[b].y), 0.f);
            float inter = iw * ih;
            float uni = ra + carea[b] - inter;
            if (inter > NMS_T * fmaxf(uni, 1e-9f)) bits |= (1ull << b);
        }
    }
    g_mask[(size_t)j * NW + bx] = bits;
}

// ---------------- kernel 4: greedy NMS scan (256-wide) + fused output -------
__global__ void __launch_bounds__(512) scan_kernel(float* __restrict__ out) {
    __shared__ u64 remv[NW];
    __shared__ u64 skeep[NW];
    __shared__ u64 sdiag[CH][WPC];        // 8KB diagonal block
    __shared__ u64 part[512];
    __shared__ unsigned short klist[CH];
    __shared__ int knum;
    int t = threadIdx.x;
    int V = g_V;
    int NC = (V + CH - 1) / CH;
    int NWv = (V + 63) >> 6;

    if (t == 511) g_cnt = 0;              // deterministic reset for next replay
    if (t < NW) { remv[t] = 0ull; skeep[t] = 0ull; }
    part[t] = 0ull;

    // prefetch diag block of chunk 0 (row = i>>2, word = i&3)
    u64 d0 = 0ull, d1 = 0ull;
    if (NC > 0) {
        d0 = g_mask[(size_t)(t >> 2) * NW + (t & 3)];
        d1 = g_mask[(size_t)((t + 512) >> 2) * NW + ((t + 512) & 3)];
    }
    __syncthreads();

    for (int c = 0; c < NC; c++) {
        sdiag[t >> 2][t & 3] = d0;
        sdiag[(t + 512) >> 2][(t + 512) & 3] = d1;
        // fold prev chunk's propagation partials into remv (word c*WPC + t)
        if (t < NW) {
            int w = c * WPC + t;
            if (w < NW)
                remv[w] |= (part[t * 4] | part[t * 4 + 1]) |
                           (part[t * 4 + 2] | part[t * 4 + 3]);
        }
        __syncthreads();

        // prefetch next chunk's diag block
        if (c + 1 < NC) {
            int base = (c + 1) * CH;
            d0 = g_mask[(size_t)(base + (t >> 2)) * NW + ((c + 1) * WPC + (t & 3))];
            d1 = g_mask[(size_t)(base + ((t + 512) >> 2)) * NW +
                        ((c + 1) * WPC + ((t + 512) & 3))];
        }

        if (t == 0) {
            u64 alive[WPC], kept[WPC];
#pragma unroll
            for (int u = 0; u < WPC; u++) {
                int rb = V - ((c * WPC + u) << 6);
                u64 vm = (rb >= 64) ? ~0ull : (rb <= 0 ? 0ull : ((1ull << rb) - 1ull));
                alive[u] = ~remv[c * WPC + u] & vm;
                kept[u] = 0ull;
            }
            int n = 0;
            for (int w = 0; w < WPC; w++) {
                while (alive[w]) {
                    int b = __ffsll((long long)alive[w]) - 1;
                    int rr = (w << 6) + b;
                    kept[w] |= 1ull << b;
                    klist[n++] = (unsigned short)rr;
                    alive[w] &= ~(1ull << b);
                    for (int u = w; u < WPC; u++)
                        alive[u] &= ~sdiag[rr][u];
                }
            }
#pragma unroll
            for (int u = 0; u < WPC; u++) skeep[c * WPC + u] = kept[u];
            knum = n;
        }
        __syncthreads();

        // propagation: 4 threads per word, 4 accumulators (MLP 16/word)
        {
            int w = (c + 1) * WPC + (t >> 2);
            int sub = t & 3;
            u64 a0 = 0ull, a1 = 0ull, a2 = 0ull, a3 = 0ull;
            if (w < NWv) {
                const u64* bp = g_mask + (size_t)(c * CH) * NW + w;
                int n = knum;
                int i = sub;
                for (; i + 12 < n; i += 16) {
                    a0 |= bp[(size_t)klist[i] * NW];
                    a1 |= bp[(size_t)klist[i + 4] * NW];
                    a2 |= bp[(size_t)klist[i + 8] * NW];
                    a3 |= bp[(size_t)klist[i + 12] * NW];
                }
                for (; i < n; i += 4) a0 |= bp[(size_t)klist[i] * NW];
            }
            part[t] = (a0 | a1) | (a2 | a3);
        }
        __syncthreads();
    }

    // fused masked output
    for (int j = t; j < M; j += 512) {
        if (j < V) {
            float f = ((skeep[j >> 6] >> (j & 63)) & 1ull) ? 1.0f : 0.0f;
#pragma unroll
            for (int c5 = 0; c5 < 5; c5++)
                out[j * 5 + c5] = g_ds[j * 5 + c5] * f;
        } else {
#pragma unroll
            for (int c5 = 0; c5 < 5; c5++)
                out[j * 5 + c5] = 0.0f;
        }
    }
}

// ---------------- launcher ---------------------------------------------------
extern "C" void kernel_launch(void* const* d_in, const int* in_sizes, int n_in,
                              void* d_out, int out_size) {
    const float* det = (const float*)d_in[0];
    const float* off = (const float*)d_in[1];
    const float* scl = (const float*)d_in[2];
    const float* bnd = (const float*)d_in[3];
    float* out = (float*)d_out;

    prep_kernel<<<32, 256>>>(det, off, scl, bnd);
    lsort_kernel<<<NTILE, 1024>>>();
    gmerge_kernel<<<8, 512>>>(4096, 2048);      // k=4096 global stage
    lmerge_kernel<4096, false><<<NTILE, 1024>>>();
    gmerge_kernel<<<8, 512>>>(8192, 4096);      // k=8192 global stages
    gmerge_kernel<<<8, 512>>>(8192, 2048);
    lmerge_kernel<8192, true><<<NTILE, 1024>>>();
    mask_kernel<<<dim3(NW, NW), 64>>>();
    scan_kernel<<<1, 512>>>(out);
}